// round 4
// baseline (speedup 1.0000x reference)
#include <cuda_runtime.h>
#include <stdint.h>

// Shapes (compile-time constants from the reference):
//   V_m  : (2, 2, NBL=2016, NTIMES=64, NFREQS=256)  float32
//   jones: (2, 2, NANT=64,  NTIMES=64, NFREQS=256)  float32
//   ant1, ant2 : (NBL,) int32
//   out  : (2, 2, NBL, NTIMES, NFREQS) float32
//
// Per (n,t,f):  out[a][d] = sum_{b,c} j1[a][b] * V[b][c] * j2[d][c]
//             = (J1 @ V @ J2^T)[a][d]
//
// Memory layout: f contiguous, TF = 64*256 = 16384 per (plane, n).
// float4-vectorize along f. All index math in float4 units:
//   TF4 = 4096 (= 2^12), V plane stride = NBL*TF4, J plane stride = NANT*TF4.

#define NPOL   2
#define NANT   64
#define NBL    2016
#define NTIMES 64
#define NFREQS 256

#define TF4    4096                 // (NTIMES*NFREQS)/4
#define SV4    (NBL * TF4)          // 8257536  V/out pol-plane stride (float4)
#define SJ4    (NANT * TF4)         // 262144   jones pol-plane stride (float4)
#define NVEC   (NBL * TF4)          // total float4 sites = 8257536

__global__ __launch_bounds__(256)
void jones_apply_kernel(const float4* __restrict__ V,
                        const float4* __restrict__ J,
                        const int*    __restrict__ ant1,
                        const int*    __restrict__ ant2,
                        float4*       __restrict__ out)
{
    const int i = blockIdx.x * 256 + threadIdx.x;   // float4 site index
    if (i >= NVEC) return;

    const int tf = i & (TF4 - 1);   // (t*F + f)/4 within a baseline
    const int n  = i >> 12;         // baseline index

    const int a1 = __ldg(&ant1[n]);
    const int a2 = __ldg(&ant2[n]);

    const int j1off = a1 * TF4 + tf;
    const int j2off = a2 * TF4 + tf;

    // Front-batch all loads for maximum MLP.
    const float4 v00 = V[i];
    const float4 v01 = V[i + SV4];
    const float4 v10 = V[i + 2 * SV4];
    const float4 v11 = V[i + 3 * SV4];

    const float4 j1_00 = J[j1off];
    const float4 j1_01 = J[j1off + SJ4];
    const float4 j1_10 = J[j1off + 2 * SJ4];
    const float4 j1_11 = J[j1off + 3 * SJ4];

    const float4 j2_00 = J[j2off];
    const float4 j2_01 = J[j2off + SJ4];
    const float4 j2_10 = J[j2off + 2 * SJ4];
    const float4 j2_11 = J[j2off + 3 * SJ4];

    float4 o00, o01, o10, o11;

    // Per-component 2x2 congruence: T = J1*V ; O = T * J2^T
#define DO_LANE(c)                                                          \
    {                                                                       \
        const float t00 = fmaf(j1_00.c, v00.c, j1_01.c * v10.c);            \
        const float t01 = fmaf(j1_00.c, v01.c, j1_01.c * v11.c);            \
        const float t10 = fmaf(j1_10.c, v00.c, j1_11.c * v10.c);            \
        const float t11 = fmaf(j1_10.c, v01.c, j1_11.c * v11.c);            \
        o00.c = fmaf(t00, j2_00.c, t01 * j2_01.c);                          \
        o01.c = fmaf(t00, j2_10.c, t01 * j2_11.c);                          \
        o10.c = fmaf(t10, j2_00.c, t11 * j2_01.c);                          \
        o11.c = fmaf(t10, j2_10.c, t11 * j2_11.c);                          \
    }

    DO_LANE(x)
    DO_LANE(y)
    DO_LANE(z)
    DO_LANE(w)
#undef DO_LANE

    out[i]           = o00;
    out[i + SV4]     = o01;
    out[i + 2 * SV4] = o10;
    out[i + 3 * SV4] = o11;
}

extern "C" void kernel_launch(void* const* d_in, const int* in_sizes, int n_in,
                              void* d_out, int out_size)
{
    const float4* V    = (const float4*)d_in[0];  // V_m   float32
    const float4* J    = (const float4*)d_in[1];  // jones float32
    const int*    ant1 = (const int*)d_in[2];
    const int*    ant2 = (const int*)d_in[3];
    float4*       out  = (float4*)d_out;

    const int blocks = (NVEC + 255) / 256;        // 32256
    jones_apply_kernel<<<blocks, 256>>>(V, J, ant1, ant2, out);
}

// round 7
// speedup vs baseline: 1.0206x; 1.0206x over previous
#include <cuda_runtime.h>
#include <stdint.h>

// V_m  : (2, 2, NBL=2016, NTIMES=64, NFREQS=256)  float32   read-once  -> evict_first (.cs)
// jones: (2, 2, NANT=64,  NTIMES=64, NFREQS=256)  float32   16.8MB, ~31x reuse -> L2 evict_last
// out  : same shape as V_m                                   write-once -> streaming store (.cs)
//
// Per (n,t,f):  out = J1 @ V @ J2^T  (2x2 real congruence), float4-vectorized over f.

#define NANT   64
#define NBL    2016

#define TF4    4096                 // (64*256)/4 float4 per (plane, n)
#define SV4    (NBL * TF4)          // V/out pol-plane stride (float4)
#define SJ4    (NANT * TF4)         // jones pol-plane stride (float4)
#define NVEC   (NBL * TF4)          // 8257536 float4 sites

// Read-once stream: evict-first in both L1 and L2.
static __device__ __forceinline__ float4 ld_stream(const float4* p)
{
    float4 v;
    asm("ld.global.cs.v4.f32 {%0,%1,%2,%3}, [%4];"
        : "=f"(v.x), "=f"(v.y), "=f"(v.z), "=f"(v.w) : "l"(p));
    return v;
}

// Heavily-reused small table: non-coherent path, pin in L2 via cache-hint policy.
static __device__ __forceinline__ float4 ld_resident(const float4* p, uint64_t pol)
{
    float4 v;
    asm("ld.global.nc.L2::cache_hint.v4.f32 {%0,%1,%2,%3}, [%4], %5;"
        : "=f"(v.x), "=f"(v.y), "=f"(v.z), "=f"(v.w) : "l"(p), "l"(pol));
    return v;
}

// Write-once stream: streaming store.
static __device__ __forceinline__ void st_stream(float4* p, float4 v)
{
    asm volatile("st.global.cs.v4.f32 [%0], {%1,%2,%3,%4};"
                 :: "l"(p), "f"(v.x), "f"(v.y), "f"(v.z), "f"(v.w));
}

__global__ __launch_bounds__(256, 6)
void jones_apply_kernel(const float4* __restrict__ V,
                        const float4* __restrict__ J,
                        const int*    __restrict__ ant1,
                        const int*    __restrict__ ant2,
                        float4*       __restrict__ out)
{
    const int i = blockIdx.x * 256 + threadIdx.x;   // float4 site index
    if (i >= NVEC) return;

    // L2 evict_last policy for the jones table (fraction = 1.0).
    uint64_t pol;
    asm("createpolicy.fractional.L2::evict_last.b64 %0, 1.0;" : "=l"(pol));

    const int tf = i & (TF4 - 1);
    const int n  = i >> 12;

    const int a1 = __ldg(&ant1[n]);
    const int a2 = __ldg(&ant2[n]);

    const int j1off = a1 * TF4 + tf;
    const int j2off = a2 * TF4 + tf;

    // Front-batch all 12 loads for maximum MLP.
    const float4 v00 = ld_stream(V + i);
    const float4 v01 = ld_stream(V + i + SV4);
    const float4 v10 = ld_stream(V + i + 2 * SV4);
    const float4 v11 = ld_stream(V + i + 3 * SV4);

    const float4 j1_00 = ld_resident(J + j1off,           pol);
    const float4 j1_01 = ld_resident(J + j1off + SJ4,     pol);
    const float4 j1_10 = ld_resident(J + j1off + 2 * SJ4, pol);
    const float4 j1_11 = ld_resident(J + j1off + 3 * SJ4, pol);

    const float4 j2_00 = ld_resident(J + j2off,           pol);
    const float4 j2_01 = ld_resident(J + j2off + SJ4,     pol);
    const float4 j2_10 = ld_resident(J + j2off + 2 * SJ4, pol);
    const float4 j2_11 = ld_resident(J + j2off + 3 * SJ4, pol);

    float4 o00, o01, o10, o11;

#define DO_LANE(c)                                                          \
    {                                                                       \
        const float t00 = fmaf(j1_00.c, v00.c, j1_01.c * v10.c);            \
        const float t01 = fmaf(j1_00.c, v01.c, j1_01.c * v11.c);            \
        const float t10 = fmaf(j1_10.c, v00.c, j1_11.c * v10.c);            \
        const float t11 = fmaf(j1_10.c, v01.c, j1_11.c * v11.c);            \
        o00.c = fmaf(t00, j2_00.c, t01 * j2_01.c);                          \
        o01.c = fmaf(t00, j2_10.c, t01 * j2_11.c);                          \
        o10.c = fmaf(t10, j2_00.c, t11 * j2_01.c);                          \
        o11.c = fmaf(t10, j2_10.c, t11 * j2_11.c);                          \
    }

    DO_LANE(x)
    DO_LANE(y)
    DO_LANE(z)
    DO_LANE(w)
#undef DO_LANE

    st_stream(out + i,           o00);
    st_stream(out + i + SV4,     o01);
    st_stream(out + i + 2 * SV4, o10);
    st_stream(out + i + 3 * SV4, o11);
}

extern "C" void kernel_launch(void* const* d_in, const int* in_sizes, int n_in,
                              void* d_out, int out_size)
{
    const float4* V    = (const float4*)d_in[0];
    const float4* J    = (const float4*)d_in[1];
    const int*    ant1 = (const int*)d_in[2];
    const int*    ant2 = (const int*)d_in[3];
    float4*       out  = (float4*)d_out;

    const int blocks = (NVEC + 255) / 256;        // 32256
    jones_apply_kernel<<<blocks, 256>>>(V, J, ant1, ant2, out);
}

// round 8
// speedup vs baseline: 1.0218x; 1.0012x over previous
#include <cuda_runtime.h>
#include <stdint.h>

// V_m  : (2, 2, NBL=2016, NTIMES=64, NFREQS=256)  float32   read-once  -> evict_first (.cs)
// jones: (2, 2, NANT=64,  NTIMES=64, NFREQS=256)  float32   16.8MB, ~31x reuse -> L2 evict_last
// out  : same shape as V_m                                   write-once -> streaming store (.cs)
//
// Per (n,t,f):  out = J1 @ V @ J2^T  (2x2 real congruence), float4-vectorized over f.

#define NANT   64
#define NBL    2016

#define TF4    4096                 // (64*256)/4 float4 per (plane, n)
#define SV4    (NBL * TF4)          // V/out pol-plane stride (float4)
#define SJ4    (NANT * TF4)         // jones pol-plane stride (float4)
#define NVEC   (NBL * TF4)          // 8257536 float4 sites

// Read-once stream: evict-first in both L1 and L2.
static __device__ __forceinline__ float4 ld_stream(const float4* p)
{
    float4 v;
    asm("ld.global.cs.v4.f32 {%0,%1,%2,%3}, [%4];"
        : "=f"(v.x), "=f"(v.y), "=f"(v.z), "=f"(v.w) : "l"(p));
    return v;
}

// Heavily-reused small table: non-coherent path, pin in L2 via cache-hint policy.
static __device__ __forceinline__ float4 ld_resident(const float4* p, uint64_t pol)
{
    float4 v;
    asm("ld.global.nc.L2::cache_hint.v4.f32 {%0,%1,%2,%3}, [%4], %5;"
        : "=f"(v.x), "=f"(v.y), "=f"(v.z), "=f"(v.w) : "l"(p), "l"(pol));
    return v;
}

// Write-once stream: streaming store.
static __device__ __forceinline__ void st_stream(float4* p, float4 v)
{
    asm volatile("st.global.cs.v4.f32 [%0], {%1,%2,%3,%4};"
                 :: "l"(p), "f"(v.x), "f"(v.y), "f"(v.z), "f"(v.w));
}

__global__ __launch_bounds__(256, 6)
void jones_apply_kernel(const float4* __restrict__ V,
                        const float4* __restrict__ J,
                        const int*    __restrict__ ant1,
                        const int*    __restrict__ ant2,
                        float4*       __restrict__ out)
{
    const int i = blockIdx.x * 256 + threadIdx.x;   // float4 site index
    if (i >= NVEC) return;

    // L2 evict_last policy for the jones table (fraction = 1.0).
    uint64_t pol;
    asm("createpolicy.fractional.L2::evict_last.b64 %0, 1.0;" : "=l"(pol));

    const int tf = i & (TF4 - 1);
    const int n  = i >> 12;

    const int a1 = __ldg(&ant1[n]);
    const int a2 = __ldg(&ant2[n]);

    const int j1off = a1 * TF4 + tf;
    const int j2off = a2 * TF4 + tf;

    // Front-batch all 12 loads for maximum MLP.
    const float4 v00 = ld_stream(V + i);
    const float4 v01 = ld_stream(V + i + SV4);
    const float4 v10 = ld_stream(V + i + 2 * SV4);
    const float4 v11 = ld_stream(V + i + 3 * SV4);

    const float4 j1_00 = ld_resident(J + j1off,           pol);
    const float4 j1_01 = ld_resident(J + j1off + SJ4,     pol);
    const float4 j1_10 = ld_resident(J + j1off + 2 * SJ4, pol);
    const float4 j1_11 = ld_resident(J + j1off + 3 * SJ4, pol);

    const float4 j2_00 = ld_resident(J + j2off,           pol);
    const float4 j2_01 = ld_resident(J + j2off + SJ4,     pol);
    const float4 j2_10 = ld_resident(J + j2off + 2 * SJ4, pol);
    const float4 j2_11 = ld_resident(J + j2off + 3 * SJ4, pol);

    float4 o00, o01, o10, o11;

#define DO_LANE(c)                                                          \
    {                                                                       \
        const float t00 = fmaf(j1_00.c, v00.c, j1_01.c * v10.c);            \
        const float t01 = fmaf(j1_00.c, v01.c, j1_01.c * v11.c);            \
        const float t10 = fmaf(j1_10.c, v00.c, j1_11.c * v10.c);            \
        const float t11 = fmaf(j1_10.c, v01.c, j1_11.c * v11.c);            \
        o00.c = fmaf(t00, j2_00.c, t01 * j2_01.c);                          \
        o01.c = fmaf(t00, j2_10.c, t01 * j2_11.c);                          \
        o10.c = fmaf(t10, j2_00.c, t11 * j2_01.c);                          \
        o11.c = fmaf(t10, j2_10.c, t11 * j2_11.c);                          \
    }

    DO_LANE(x)
    DO_LANE(y)
    DO_LANE(z)
    DO_LANE(w)
#undef DO_LANE

    st_stream(out + i,           o00);
    st_stream(out + i + SV4,     o01);
    st_stream(out + i + 2 * SV4, o10);
    st_stream(out + i + 3 * SV4, o11);
}

extern "C" void kernel_launch(void* const* d_in, const int* in_sizes, int n_in,
                              void* d_out, int out_size)
{
    const float4* V    = (const float4*)d_in[0];
    const float4* J    = (const float4*)d_in[1];
    const int*    ant1 = (const int*)d_in[2];
    const int*    ant2 = (const int*)d_in[3];
    float4*       out  = (float4*)d_out;

    const int blocks = (NVEC + 255) / 256;        // 32256
    jones_apply_kernel<<<blocks, 256>>>(V, J, ant1, ant2, out);
}